// round 2
// baseline (speedup 1.0000x reference)
#include <cuda_runtime.h>

#define HH 256
#define WW 256
#define HW 65536
#define BS 8
#define IC 16
#define OC 32
#define NSTEPS 7

// Scratch (static device globals — no runtime allocation).
__device__ float g_raw[BS * OC * HW];          // conv output / ping-pong buffer
__device__ float g_vec[BS * OC * HW];          // ping-pong buffer
__device__ float g_part[2][OC][2048];          // per-block partial (sum, sumsq)
__device__ float g_affa[OC];                   // BN affine scale (incl. 1/128)
__device__ float g_affb[OC];                   // BN affine shift (incl. 1/128)

// ---------------------------------------------------------------------------
// Conv 3x3 (16->32, pad 1) + deterministic per-block channel stats.
// grid (8 xtiles, 32 ytiles, 8 batch), block 256 = 8 warps.
// Tile 32 wide x 8 tall. Warp w owns oc [4w, 4w+4); lane = x; each thread
// computes an 8-row column strip -> 4 oc x 8 px = 32 outputs/thread.
// FFMA:LDS ~ 4.4:1 so we sit on the FMA pipe, not the smem crossbar.
// ---------------------------------------------------------------------------
__global__ __launch_bounds__(256) void conv_kernel(const float* __restrict__ f,
                                                   const float* __restrict__ vw,
                                                   const float* __restrict__ vb) {
    __shared__ float ft[IC * 10 * 34];   // f tile + halo: 16ch x 10 rows x 34 cols
    __shared__ float ws[OC * 144];       // all weights

    const int tid  = threadIdx.x;
    const int lane = tid & 31;
    const int wid  = tid >> 5;
    const int x0   = blockIdx.x * 32;
    const int y0   = blockIdx.y * 8;
    const int b    = blockIdx.z;

    for (int i = tid; i < OC * 144; i += 256) ws[i] = vw[i];

    const float* fb = f + (size_t)b * IC * HW;
    for (int i = tid; i < IC * 10 * 34; i += 256) {
        int ic = i / 340;
        int rem = i % 340;
        int r = rem / 34, cc = rem % 34;
        int yy = y0 - 1 + r, xx = x0 - 1 + cc;
        float v = 0.f;
        if (yy >= 0 && yy < HH && xx >= 0 && xx < WW) v = fb[ic * HW + yy * WW + xx];
        ft[i] = v;
    }
    __syncthreads();

    const int oc0 = wid * 4;
    float acc[4][8];
#pragma unroll
    for (int i = 0; i < 4; i++) {
        float bias = vb[oc0 + i];
#pragma unroll
        for (int j = 0; j < 8; j++) acc[i][j] = bias;
    }

    for (int ic = 0; ic < IC; ic++) {
        const float* ftc = ft + ic * 340;
#pragma unroll
        for (int kx = 0; kx < 3; kx++) {
            float col[10];
#pragma unroll
            for (int r = 0; r < 10; r++) col[r] = ftc[r * 34 + lane + kx];
            float wv[4][3];
#pragma unroll
            for (int i = 0; i < 4; i++)
#pragma unroll
                for (int ky = 0; ky < 3; ky++)
                    wv[i][ky] = ws[(oc0 + i) * 144 + ic * 9 + ky * 3 + kx];
#pragma unroll
            for (int i = 0; i < 4; i++)
#pragma unroll
                for (int j = 0; j < 8; j++)
                    acc[i][j] += col[j] * wv[i][0] + col[j + 1] * wv[i][1] + col[j + 2] * wv[i][2];
        }
    }

    // Store results (coalesced: lanes are consecutive x) + deterministic partials.
    const int blk = (b * (int)gridDim.y + blockIdx.y) * (int)gridDim.x + blockIdx.x;
#pragma unroll
    for (int i = 0; i < 4; i++) {
        float s = 0.f, s2 = 0.f;
        float* dst = g_raw + (size_t)(b * OC + oc0 + i) * HW + y0 * WW + x0 + lane;
#pragma unroll
        for (int j = 0; j < 8; j++) {
            float v = acc[i][j];
            dst[j * WW] = v;
            s += v;
            s2 += v * v;
        }
#pragma unroll
        for (int off = 16; off > 0; off >>= 1) {
            s  += __shfl_down_sync(0xffffffffu, s, off);
            s2 += __shfl_down_sync(0xffffffffu, s2, off);
        }
        if (lane == 0) {
            g_part[0][oc0 + i][blk] = s;
            g_part[1][oc0 + i][blk] = s2;
        }
    }
}

// ---------------------------------------------------------------------------
// Reduce partials -> BN affine (gamma*rsqrt(var+eps), shift), folded with the
// VecInt 1/2^NSTEPS scale. Deterministic tree reduce.
// ---------------------------------------------------------------------------
__global__ __launch_bounds__(256) void stats_kernel(const float* __restrict__ gamma,
                                                    const float* __restrict__ beta) {
    __shared__ float sm[256], sm2[256];
    const int ch = blockIdx.x, tid = threadIdx.x;
    float s = 0.f, s2 = 0.f;
    for (int i = tid; i < 2048; i += 256) {
        s += g_part[0][ch][i];
        s2 += g_part[1][ch][i];
    }
    sm[tid] = s; sm2[tid] = s2;
    __syncthreads();
    for (int off = 128; off > 0; off >>= 1) {
        if (tid < off) { sm[tid] += sm[tid + off]; sm2[tid] += sm2[tid + off]; }
        __syncthreads();
    }
    if (tid == 0) {
        const float n = (float)(BS * HW);
        float mean = sm[0] / n;
        float var = sm2[0] / n - mean * mean;
        float r = rsqrtf(var + 1e-5f);
        const float scale = 1.0f / 128.0f;   // 1 / 2^NSTEPS
        g_affa[ch] = gamma[ch] * r * scale;
        g_affb[ch] = (beta[ch] - gamma[ch] * mean * r) * scale;
    }
}

// ---------------------------------------------------------------------------
// One scaling-and-squaring step, fully fused:
//   newvec = vec + warp(vec, vec)              (write to ping-pong buffer)
//   m      = warp(f[b,c], newvec)              (per-channel bilinear of f)
//   out[b,o,p] (+)= sum_c fuse_w[o,c,step]*m   (per-pixel channel mix)
// FIRST step also applies the BN affine on every vec load (reading raw conv
// output) and initializes out with fuse_b.
// Thread per (batch, pixel); loops over the 16 flow channels.
// ---------------------------------------------------------------------------
template <bool FIRST>
__global__ __launch_bounds__(256) void step_kernel(const float* __restrict__ f,
                                                   const float* __restrict__ fw,
                                                   const float* __restrict__ fbias,
                                                   float* __restrict__ out,
                                                   int step) {
    __shared__ float ws[256];   // fuse_w[o][c] for this step
    __shared__ float fb_s[16];
    const int tid = threadIdx.x;
    ws[tid] = fw[tid * NSTEPS + step];   // tid = o*16 + c ; layout (o,c,s)
    if (tid < 16) fb_s[tid] = fbias[tid];
    __syncthreads();

    const int gid = blockIdx.x * 256 + tid;
    const int b = gid >> 16;
    const int p = gid & 65535;
    const int y = p >> 8, x = p & 255;
    const float fy = (float)y, fx = (float)x;

    const float* vin = (step & 1) ? g_vec : g_raw;
    float* vout      = (step & 1) ? g_raw : g_vec;

    float acc[16];
#pragma unroll
    for (int o = 0; o < 16; o++) acc[o] = 0.f;

    for (int c = 0; c < 16; c++) {
        const float* pdy = vin + (size_t)(b * OC + 2 * c) * HW;
        const float* pdx = pdy + HW;
        float a0 = 1.f, b0 = 0.f, a1 = 1.f, b1 = 0.f;
        if (FIRST) {
            a0 = g_affa[2 * c]; b0 = g_affb[2 * c];
            a1 = g_affa[2 * c + 1]; b1 = g_affb[2 * c + 1];
        }
        float dy = pdy[p], dx = pdx[p];
        if (FIRST) { dy = a0 * dy + b0; dx = a1 * dx + b1; }

        // ---- warp(vec, vec): bilinear self-sample at (y+dy, x+dx), zero pad
        float py = fy + dy, px = fx + dx;
        float y0f = floorf(py), x0f = floorf(px);
        float wy1 = py - y0f, wy0 = 1.f - wy1;
        float wx1 = px - x0f, wx0 = 1.f - wx1;
        int yi = (int)y0f, xi = (int)x0f;
        float wdy = 0.f, wdx = 0.f;
#pragma unroll
        for (int t = 0; t < 4; t++) {
            int ty = yi + (t >> 1), tx = xi + (t & 1);
            float wgt = ((t >> 1) ? wy1 : wy0) * ((t & 1) ? wx1 : wx0);
            if ((unsigned)ty < (unsigned)HH && (unsigned)tx < (unsigned)WW) {
                int ii = ty * WW + tx;
                float vdy = pdy[ii], vdx = pdx[ii];
                if (FIRST) { vdy = a0 * vdy + b0; vdx = a1 * vdx + b1; }
                wdy += wgt * vdy;
                wdx += wgt * vdx;
            }
        }
        float ndy = dy + wdy, ndx = dx + wdx;
        vout[(size_t)(b * OC + 2 * c) * HW + p] = ndy;
        vout[(size_t)(b * OC + 2 * c + 1) * HW + p] = ndx;

        // ---- warp(f[b,c], newvec): bilinear sample of f, zero pad
        const float* fp = f + (size_t)(b * IC + c) * HW;
        float qy = fy + ndy, qx = fx + ndx;
        float qy0 = floorf(qy), qx0 = floorf(qx);
        float vy1 = qy - qy0, vy0 = 1.f - vy1;
        float vx1 = qx - qx0, vx0 = 1.f - vx1;
        int qyi = (int)qy0, qxi = (int)qx0;
        float m = 0.f;
#pragma unroll
        for (int t = 0; t < 4; t++) {
            int ty = qyi + (t >> 1), tx = qxi + (t & 1);
            float wgt = ((t >> 1) ? vy1 : vy0) * ((t & 1) ? vx1 : vx0);
            if ((unsigned)ty < (unsigned)HH && (unsigned)tx < (unsigned)WW)
                m += wgt * fp[ty * WW + tx];
        }

        // ---- fuse accumulation
#pragma unroll
        for (int o = 0; o < 16; o++) acc[o] += ws[o * 16 + c] * m;
    }

    float* op = out + (size_t)b * IC * HW + p;
    if (FIRST) {
#pragma unroll
        for (int o = 0; o < 16; o++) op[o * HW] = acc[o] + fb_s[o];
    } else {
#pragma unroll
        for (int o = 0; o < 16; o++) op[o * HW] += acc[o];
    }
}

extern "C" void kernel_launch(void* const* d_in, const int* in_sizes, int n_in,
                              void* d_out, int out_size) {
    const float* f     = (const float*)d_in[0];
    const float* vw    = (const float*)d_in[1];
    const float* vb    = (const float*)d_in[2];
    const float* gamma = (const float*)d_in[3];
    const float* beta  = (const float*)d_in[4];
    const float* fw    = (const float*)d_in[5];
    const float* fbias = (const float*)d_in[6];
    float* out = (float*)d_out;

    dim3 cg(8, 32, 8);
    conv_kernel<<<cg, 256>>>(f, vw, vb);
    stats_kernel<<<32, 256>>>(gamma, beta);
    step_kernel<true><<<2048, 256>>>(f, fw, fbias, out, 0);
    for (int s = 1; s < NSTEPS; s++)
        step_kernel<false><<<2048, 256>>>(f, fw, fbias, out, s);
}

// round 3
// speedup vs baseline: 1.1616x; 1.1616x over previous
#include <cuda_runtime.h>

#define HH 256
#define WW 256
#define HW 65536
#define BS 8
#define IC 16
#define OC 32
#define NSTEPS 7

// Scratch (static device globals — no runtime allocation).
__device__ __align__(16) float  g_raw[BS * OC * HW];   // conv output (planar)
__device__ __align__(16) float2 g_fA[BS * IC * HW];    // interleaved flow ping
__device__ __align__(16) float2 g_fB[BS * IC * HW];    // interleaved flow pong
__device__ float g_part[2][OC][2048];                  // per-block partial (sum, sumsq)
__device__ float g_affa[OC];                           // BN affine scale (incl. 1/128)
__device__ float g_affb[OC];                           // BN affine shift (incl. 1/128)

// ---------------------------------------------------------------------------
// Conv 3x3 (16->32, pad 1) + deterministic per-block channel stats.
// ---------------------------------------------------------------------------
__global__ __launch_bounds__(256) void conv_kernel(const float* __restrict__ f,
                                                   const float* __restrict__ vw,
                                                   const float* __restrict__ vb) {
    __shared__ float ft[IC * 10 * 34];
    __shared__ float ws[OC * 144];

    const int tid  = threadIdx.x;
    const int lane = tid & 31;
    const int wid  = tid >> 5;
    const int x0   = blockIdx.x * 32;
    const int y0   = blockIdx.y * 8;
    const int b    = blockIdx.z;

    for (int i = tid; i < OC * 144; i += 256) ws[i] = vw[i];

    const float* fb = f + (size_t)b * IC * HW;
    for (int i = tid; i < IC * 10 * 34; i += 256) {
        int ic = i / 340;
        int rem = i % 340;
        int r = rem / 34, cc = rem % 34;
        int yy = y0 - 1 + r, xx = x0 - 1 + cc;
        float v = 0.f;
        if (yy >= 0 && yy < HH && xx >= 0 && xx < WW) v = fb[ic * HW + yy * WW + xx];
        ft[i] = v;
    }
    __syncthreads();

    const int oc0 = wid * 4;
    float acc[4][8];
#pragma unroll
    for (int i = 0; i < 4; i++) {
        float bias = vb[oc0 + i];
#pragma unroll
        for (int j = 0; j < 8; j++) acc[i][j] = bias;
    }

    for (int ic = 0; ic < IC; ic++) {
        const float* ftc = ft + ic * 340;
#pragma unroll
        for (int kx = 0; kx < 3; kx++) {
            float col[10];
#pragma unroll
            for (int r = 0; r < 10; r++) col[r] = ftc[r * 34 + lane + kx];
            float wv[4][3];
#pragma unroll
            for (int i = 0; i < 4; i++)
#pragma unroll
                for (int ky = 0; ky < 3; ky++)
                    wv[i][ky] = ws[(oc0 + i) * 144 + ic * 9 + ky * 3 + kx];
#pragma unroll
            for (int i = 0; i < 4; i++)
#pragma unroll
                for (int j = 0; j < 8; j++)
                    acc[i][j] += col[j] * wv[i][0] + col[j + 1] * wv[i][1] + col[j + 2] * wv[i][2];
        }
    }

    const int blk = (b * (int)gridDim.y + blockIdx.y) * (int)gridDim.x + blockIdx.x;
#pragma unroll
    for (int i = 0; i < 4; i++) {
        float s = 0.f, s2 = 0.f;
        float* dst = g_raw + (size_t)(b * OC + oc0 + i) * HW + y0 * WW + x0 + lane;
#pragma unroll
        for (int j = 0; j < 8; j++) {
            float v = acc[i][j];
            dst[j * WW] = v;
            s += v;
            s2 += v * v;
        }
#pragma unroll
        for (int off = 16; off > 0; off >>= 1) {
            s  += __shfl_down_sync(0xffffffffu, s, off);
            s2 += __shfl_down_sync(0xffffffffu, s2, off);
        }
        if (lane == 0) {
            g_part[0][oc0 + i][blk] = s;
            g_part[1][oc0 + i][blk] = s2;
        }
    }
}

// ---------------------------------------------------------------------------
// Reduce partials -> BN affine, folded with 1/2^NSTEPS.
// ---------------------------------------------------------------------------
__global__ __launch_bounds__(256) void stats_kernel(const float* __restrict__ gamma,
                                                    const float* __restrict__ beta) {
    __shared__ float sm[256], sm2[256];
    const int ch = blockIdx.x, tid = threadIdx.x;
    float s = 0.f, s2 = 0.f;
    for (int i = tid; i < 2048; i += 256) {
        s += g_part[0][ch][i];
        s2 += g_part[1][ch][i];
    }
    sm[tid] = s; sm2[tid] = s2;
    __syncthreads();
    for (int off = 128; off > 0; off >>= 1) {
        if (tid < off) { sm[tid] += sm[tid + off]; sm2[tid] += sm2[tid + off]; }
        __syncthreads();
    }
    if (tid == 0) {
        const float n = (float)(BS * HW);
        float mean = sm[0] / n;
        float var = sm2[0] / n - mean * mean;
        float r = rsqrtf(var + 1e-5f);
        const float scale = 1.0f / 128.0f;
        g_affa[ch] = gamma[ch] * r * scale;
        g_affb[ch] = (beta[ch] - gamma[ch] * mean * r) * scale;
    }
}

// ---------------------------------------------------------------------------
// One fused scaling-and-squaring step. 2 pixels per thread (aligned pair).
// Flow stored interleaved (float2 = dy,dx) -> every bilinear tap is one LDG.64,
// the center read of both pixels is one LDG.128, vout store is one STG.128.
// Fuse weights in smem transposed [c][o], read as float4 -> 4 LDS per (c,pair).
// out accumulated as float2 RMW.
// FIRST step reads planar conv output + applies BN affine on every tap.
// ---------------------------------------------------------------------------
template <bool FIRST>
__global__ __launch_bounds__(256) void step_kernel(const float* __restrict__ f,
                                                   const float* __restrict__ fw,
                                                   const float* __restrict__ fbias,
                                                   float* __restrict__ out,
                                                   int step) {
    __shared__ __align__(16) float ws[256];   // [c][o]
    __shared__ float fb_s[16];
    const int tid = threadIdx.x;
    {
        int o = tid & 15, c = tid >> 4;
        ws[c * 16 + o] = fw[(o * 16 + c) * NSTEPS + step];
    }
    if (tid < 16) fb_s[tid] = fbias[tid];
    __syncthreads();

    const int gid = blockIdx.x * 256 + tid;
    const int pix = gid * 2;
    const int b = pix >> 16;
    const int p = pix & 65535;          // even
    const int y = p >> 8, x = p & 255;  // x even, pair is (x, x+1) same row
    const float fy = (float)y;
    const float fx0 = (float)x, fx1 = (float)(x + 1);

    const float2* vin = (step & 1) ? g_fA : g_fB;   // unused when FIRST
    float2* vout      = FIRST ? g_fA : ((step & 1) ? g_fB : g_fA);

    float acc0[16], acc1[16];
#pragma unroll
    for (int o = 0; o < 16; o++) { acc0[o] = 0.f; acc1[o] = 0.f; }

    for (int c = 0; c < 16; c++) {
        const float* pdy = nullptr;
        const float* pdx = nullptr;
        const float2* pc = nullptr;
        float a0 = 0.f, b0 = 0.f, a1 = 0.f, b1 = 0.f;
        float dy0, dx0, dy1, dx1;
        if (FIRST) {
            pdy = g_raw + (size_t)(b * OC + 2 * c) * HW;
            pdx = pdy + HW;
            a0 = g_affa[2 * c];     b0 = g_affb[2 * c];
            a1 = g_affa[2 * c + 1]; b1 = g_affb[2 * c + 1];
            float2 cy = *(const float2*)(pdy + p);
            float2 cx = *(const float2*)(pdx + p);
            dy0 = a0 * cy.x + b0; dy1 = a0 * cy.y + b0;
            dx0 = a1 * cx.x + b1; dx1 = a1 * cx.y + b1;
        } else {
            pc = vin + (size_t)(b * IC + c) * HW;
            float4 cv = *(const float4*)(pc + p);
            dy0 = cv.x; dx0 = cv.y; dy1 = cv.z; dx1 = cv.w;
        }

        float ndy[2], ndx[2];
#pragma unroll
        for (int j = 0; j < 2; j++) {
            float dy = j ? dy1 : dy0;
            float dx = j ? dx1 : dx0;
            float py = fy + dy;
            float px = (j ? fx1 : fx0) + dx;
            float yf = floorf(py), xf = floorf(px);
            float wy1 = py - yf, wy0 = 1.f - wy1;
            float wx1 = px - xf, wx0 = 1.f - wx1;
            int yi = (int)yf, xi = (int)xf;
            float wdy = 0.f, wdx = 0.f;
#pragma unroll
            for (int t = 0; t < 4; t++) {
                int ty = yi + (t >> 1), tx = xi + (t & 1);
                float wgt = ((t >> 1) ? wy1 : wy0) * ((t & 1) ? wx1 : wx0);
                if ((unsigned)ty < (unsigned)HH && (unsigned)tx < (unsigned)WW) {
                    if (FIRST) {
                        int ii = ty * WW + tx;
                        wdy += wgt * (a0 * pdy[ii] + b0);
                        wdx += wgt * (a1 * pdx[ii] + b1);
                    } else {
                        float2 v = pc[ty * WW + tx];
                        wdy += wgt * v.x;
                        wdx += wgt * v.y;
                    }
                }
            }
            ndy[j] = dy + wdy;
            ndx[j] = dx + wdx;
        }

        // store new flow (interleaved, both pixels in one 16B store)
        float4 sv;
        sv.x = ndy[0]; sv.y = ndx[0]; sv.z = ndy[1]; sv.w = ndx[1];
        *(float4*)(vout + (size_t)(b * IC + c) * HW + p) = sv;

        // warp f[b,c] by the new flow (bilinear, zero pad)
        const float* fp = f + (size_t)(b * IC + c) * HW;
        float m[2];
#pragma unroll
        for (int j = 0; j < 2; j++) {
            float qy = fy + ndy[j];
            float qx = (j ? fx1 : fx0) + ndx[j];
            float yf = floorf(qy), xf = floorf(qx);
            float vy1 = qy - yf, vy0 = 1.f - vy1;
            float vx1 = qx - xf, vx0 = 1.f - vx1;
            int yi = (int)yf, xi = (int)xf;
            float mm = 0.f;
#pragma unroll
            for (int t = 0; t < 4; t++) {
                int ty = yi + (t >> 1), tx = xi + (t & 1);
                float wgt = ((t >> 1) ? vy1 : vy0) * ((t & 1) ? vx1 : vx0);
                if ((unsigned)ty < (unsigned)HH && (unsigned)tx < (unsigned)WW)
                    mm += wgt * fp[ty * WW + tx];
            }
            m[j] = mm;
        }

        // fuse accumulation: weights as float4 LDS, broadcast across warp
#pragma unroll
        for (int g = 0; g < 4; g++) {
            float4 wv = *(const float4*)(ws + c * 16 + g * 4);
            acc0[g * 4 + 0] += wv.x * m[0]; acc1[g * 4 + 0] += wv.x * m[1];
            acc0[g * 4 + 1] += wv.y * m[0]; acc1[g * 4 + 1] += wv.y * m[1];
            acc0[g * 4 + 2] += wv.z * m[0]; acc1[g * 4 + 2] += wv.z * m[1];
            acc0[g * 4 + 3] += wv.w * m[0]; acc1[g * 4 + 3] += wv.w * m[1];
        }
    }

    float* op = out + (size_t)b * IC * HW + p;
    if (FIRST) {
#pragma unroll
        for (int o = 0; o < 16; o++) {
            float2 v;
            v.x = acc0[o] + fb_s[o];
            v.y = acc1[o] + fb_s[o];
            *(float2*)(op + o * HW) = v;
        }
    } else {
#pragma unroll
        for (int o = 0; o < 16; o++) {
            float2* q = (float2*)(op + o * HW);
            float2 v = *q;
            v.x += acc0[o];
            v.y += acc1[o];
            *q = v;
        }
    }
}

extern "C" void kernel_launch(void* const* d_in, const int* in_sizes, int n_in,
                              void* d_out, int out_size) {
    const float* f     = (const float*)d_in[0];
    const float* vw    = (const float*)d_in[1];
    const float* vb    = (const float*)d_in[2];
    const float* gamma = (const float*)d_in[3];
    const float* beta  = (const float*)d_in[4];
    const float* fw    = (const float*)d_in[5];
    const float* fbias = (const float*)d_in[6];
    float* out = (float*)d_out;

    dim3 cg(8, 32, 8);
    conv_kernel<<<cg, 256>>>(f, vw, vb);
    stats_kernel<<<32, 256>>>(gamma, beta);
    // step 0 writes g_fA; step s>=1: odd reads g_fA->writes g_fB, even reads g_fB->writes g_fA
    step_kernel<true><<<1024, 256>>>(f, fw, fbias, out, 0);
    for (int s = 1; s < NSTEPS; s++)
        step_kernel<false><<<1024, 256>>>(f, fw, fbias, out, s);
}

// round 4
// speedup vs baseline: 1.3259x; 1.1415x over previous
#include <cuda_runtime.h>

#define HH 256
#define WW 256
#define HW 65536
#define BS 8
#define IC 16
#define OC 32
#define NSTEPS 7

// Scratch (static device globals — no runtime allocation).
__device__ __align__(16) float  g_raw[BS * OC * HW];   // conv output (planar)
__device__ __align__(16) float2 g_fA[BS * IC * HW];    // interleaved flow ping
__device__ __align__(16) float2 g_fB[BS * IC * HW];    // interleaved flow pong
__device__ float g_part[2][OC][2048];                  // per-block partial (sum, sumsq)
__device__ float g_affa[OC];                           // BN affine scale (incl. 1/128)
__device__ float g_affb[OC];                           // BN affine shift (incl. 1/128)

// ---------------------------------------------------------------------------
// Conv 3x3 (16->32, pad 1) + deterministic per-block channel stats.
// ---------------------------------------------------------------------------
__global__ __launch_bounds__(256) void conv_kernel(const float* __restrict__ f,
                                                   const float* __restrict__ vw,
                                                   const float* __restrict__ vb) {
    __shared__ float ft[IC * 10 * 34];
    __shared__ float ws[OC * 144];

    const int tid  = threadIdx.x;
    const int lane = tid & 31;
    const int wid  = tid >> 5;
    const int x0   = blockIdx.x * 32;
    const int y0   = blockIdx.y * 8;
    const int b    = blockIdx.z;

    for (int i = tid; i < OC * 144; i += 256) ws[i] = vw[i];

    const float* fb = f + (size_t)b * IC * HW;
    for (int i = tid; i < IC * 10 * 34; i += 256) {
        int ic = i / 340;
        int rem = i % 340;
        int r = rem / 34, cc = rem % 34;
        int yy = y0 - 1 + r, xx = x0 - 1 + cc;
        float v = 0.f;
        if (yy >= 0 && yy < HH && xx >= 0 && xx < WW) v = fb[ic * HW + yy * WW + xx];
        ft[i] = v;
    }
    __syncthreads();

    const int oc0 = wid * 4;
    float acc[4][8];
#pragma unroll
    for (int i = 0; i < 4; i++) {
        float bias = vb[oc0 + i];
#pragma unroll
        for (int j = 0; j < 8; j++) acc[i][j] = bias;
    }

    for (int ic = 0; ic < IC; ic++) {
        const float* ftc = ft + ic * 340;
#pragma unroll
        for (int kx = 0; kx < 3; kx++) {
            float col[10];
#pragma unroll
            for (int r = 0; r < 10; r++) col[r] = ftc[r * 34 + lane + kx];
            float wv[4][3];
#pragma unroll
            for (int i = 0; i < 4; i++)
#pragma unroll
                for (int ky = 0; ky < 3; ky++)
                    wv[i][ky] = ws[(oc0 + i) * 144 + ic * 9 + ky * 3 + kx];
#pragma unroll
            for (int i = 0; i < 4; i++)
#pragma unroll
                for (int j = 0; j < 8; j++)
                    acc[i][j] += col[j] * wv[i][0] + col[j + 1] * wv[i][1] + col[j + 2] * wv[i][2];
        }
    }

    const int blk = (b * (int)gridDim.y + blockIdx.y) * (int)gridDim.x + blockIdx.x;
#pragma unroll
    for (int i = 0; i < 4; i++) {
        float s = 0.f, s2 = 0.f;
        float* dst = g_raw + (size_t)(b * OC + oc0 + i) * HW + y0 * WW + x0 + lane;
#pragma unroll
        for (int j = 0; j < 8; j++) {
            float v = acc[i][j];
            dst[j * WW] = v;
            s += v;
            s2 += v * v;
        }
#pragma unroll
        for (int off = 16; off > 0; off >>= 1) {
            s  += __shfl_down_sync(0xffffffffu, s, off);
            s2 += __shfl_down_sync(0xffffffffu, s2, off);
        }
        if (lane == 0) {
            g_part[0][oc0 + i][blk] = s;
            g_part[1][oc0 + i][blk] = s2;
        }
    }
}

// ---------------------------------------------------------------------------
// Reduce partials -> BN affine, folded with 1/2^NSTEPS.
// ---------------------------------------------------------------------------
__global__ __launch_bounds__(256) void stats_kernel(const float* __restrict__ gamma,
                                                    const float* __restrict__ beta) {
    __shared__ float sm[256], sm2[256];
    const int ch = blockIdx.x, tid = threadIdx.x;
    float s = 0.f, s2 = 0.f;
    for (int i = tid; i < 2048; i += 256) {
        s += g_part[0][ch][i];
        s2 += g_part[1][ch][i];
    }
    sm[tid] = s; sm2[tid] = s2;
    __syncthreads();
    for (int off = 128; off > 0; off >>= 1) {
        if (tid < off) { sm[tid] += sm[tid + off]; sm2[tid] += sm2[tid + off]; }
        __syncthreads();
    }
    if (tid == 0) {
        const float n = (float)(BS * HW);
        float mean = sm[0] / n;
        float var = sm2[0] / n - mean * mean;
        float r = rsqrtf(var + 1e-5f);
        const float scale = 1.0f / 128.0f;
        g_affa[ch] = gamma[ch] * r * scale;
        g_affb[ch] = (beta[ch] - gamma[ch] * mean * r) * scale;
    }
}

// ---------------------------------------------------------------------------
// One fused scaling-and-squaring step, two-phase block structure.
// Block = 512 threads, tile = 32 consecutive pixels.
// Phase 1: thread (c, px) integrates flow channel c at pixel px, stores the
//          new flow (interleaved float2) and writes the warped-f sample m
//          into smem. One (c,px) per thread -> ~30 regs, high occupancy,
//          no long dependent chains per warp; gathers from 512 independent
//          threads/block hide L2 latency.
// Phase 2: thread (o, px) mixes the 16 smem m values with fuse weights and
//          RMWs the output plane (coalesced 128B rows).
// FIRST step reads planar conv output + applies BN affine on every tap,
// and initializes out with fuse bias instead of RMW.
// ---------------------------------------------------------------------------
template <bool FIRST>
__global__ __launch_bounds__(512) void step_kernel(const float* __restrict__ f,
                                                   const float* __restrict__ fw,
                                                   const float* __restrict__ fbias,
                                                   float* __restrict__ out,
                                                   int step) {
    __shared__ float ws[256];        // [o][c]
    __shared__ float fb_s[16];
    __shared__ float sm_m[16][33];   // [c][px] padded

    const int tid = threadIdx.x;
    if (tid < 256) {
        int o = tid >> 4, c = tid & 15;
        ws[o * 16 + c] = fw[(o * 16 + c) * NSTEPS + step];
    }
    if (tid < 16) fb_s[tid] = fbias[tid];

    const int pix0 = blockIdx.x * 32;
    const int b  = pix0 >> 16;
    const int p0 = pix0 & 65535;

    // ---------------- phase 1: one (channel, pixel) per thread ----------------
    {
        const int c  = tid >> 5;
        const int pj = tid & 31;
        const int p  = p0 + pj;
        const int y  = p >> 8, x = p & 255;
        const float fy = (float)y, fx = (float)x;

        float dy, dx;
        const float* pdy = nullptr;
        const float* pdx = nullptr;
        const float2* pc = nullptr;
        float a0 = 0.f, b0 = 0.f, a1 = 0.f, b1 = 0.f;
        if (FIRST) {
            pdy = g_raw + (size_t)(b * OC + 2 * c) * HW;
            pdx = pdy + HW;
            a0 = g_affa[2 * c];     b0 = g_affb[2 * c];
            a1 = g_affa[2 * c + 1]; b1 = g_affb[2 * c + 1];
            dy = a0 * pdy[p] + b0;
            dx = a1 * pdx[p] + b1;
        } else {
            pc = ((step & 1) ? g_fA : g_fB) + (size_t)(b * IC + c) * HW;
            float2 cv = pc[p];
            dy = cv.x; dx = cv.y;
        }

        // warp(vec, vec): bilinear self-sample at (y+dy, x+dx), zero pad
        float py = fy + dy, px = fx + dx;
        float yf = floorf(py), xf = floorf(px);
        float wy1 = py - yf, wy0 = 1.f - wy1;
        float wx1 = px - xf, wx0 = 1.f - wx1;
        int yi = (int)yf, xi = (int)xf;
        float wdy = 0.f, wdx = 0.f;
#pragma unroll
        for (int t = 0; t < 4; t++) {
            int ty = yi + (t >> 1), tx = xi + (t & 1);
            float wgt = ((t >> 1) ? wy1 : wy0) * ((t & 1) ? wx1 : wx0);
            if ((unsigned)ty < (unsigned)HH && (unsigned)tx < (unsigned)WW) {
                if (FIRST) {
                    int ii = ty * WW + tx;
                    wdy += wgt * (a0 * pdy[ii] + b0);
                    wdx += wgt * (a1 * pdx[ii] + b1);
                } else {
                    float2 v = pc[ty * WW + tx];
                    wdy += wgt * v.x;
                    wdx += wgt * v.y;
                }
            }
        }
        float ndy = dy + wdy, ndx = dx + wdx;

        float2* vout = (FIRST ? g_fA : ((step & 1) ? g_fB : g_fA));
        float2 sv; sv.x = ndy; sv.y = ndx;
        vout[(size_t)(b * IC + c) * HW + p] = sv;

        // warp(f[b,c], new flow): bilinear sample of f, zero pad
        const float* fp = f + (size_t)(b * IC + c) * HW;
        float qy = fy + ndy, qx = fx + ndx;
        float qyf = floorf(qy), qxf = floorf(qx);
        float vy1 = qy - qyf, vy0 = 1.f - vy1;
        float vx1 = qx - qxf, vx0 = 1.f - vx1;
        int qyi = (int)qyf, qxi = (int)qxf;
        float m = 0.f;
#pragma unroll
        for (int t = 0; t < 4; t++) {
            int ty = qyi + (t >> 1), tx = qxi + (t & 1);
            float wgt = ((t >> 1) ? vy1 : vy0) * ((t & 1) ? vx1 : vx0);
            if ((unsigned)ty < (unsigned)HH && (unsigned)tx < (unsigned)WW)
                m += wgt * fp[ty * WW + tx];
        }
        sm_m[c][pj] = m;
    }

    __syncthreads();

    // ---------------- phase 2: one (output, pixel) per thread ----------------
    {
        const int o  = tid >> 5;
        const int pj = tid & 31;
        const int p  = p0 + pj;
        float* op = out + (size_t)(b * IC + o) * HW + p;

        float acc = FIRST ? fb_s[o] : *op;
#pragma unroll
        for (int c = 0; c < 16; c++)
            acc += ws[o * 16 + c] * sm_m[c][pj];
        *op = acc;
    }
}

extern "C" void kernel_launch(void* const* d_in, const int* in_sizes, int n_in,
                              void* d_out, int out_size) {
    const float* f     = (const float*)d_in[0];
    const float* vw    = (const float*)d_in[1];
    const float* vb    = (const float*)d_in[2];
    const float* gamma = (const float*)d_in[3];
    const float* beta  = (const float*)d_in[4];
    const float* fw    = (const float*)d_in[5];
    const float* fbias = (const float*)d_in[6];
    float* out = (float*)d_out;

    dim3 cg(8, 32, 8);
    conv_kernel<<<cg, 256>>>(f, vw, vb);
    stats_kernel<<<32, 256>>>(gamma, beta);
    const int nblk = BS * HW / 32;   // 16384
    // step 0 writes g_fA; step s>=1: odd reads g_fA->writes g_fB, even reads g_fB->writes g_fA
    step_kernel<true><<<nblk, 512>>>(f, fw, fbias, out, 0);
    for (int s = 1; s < NSTEPS; s++)
        step_kernel<false><<<nblk, 512>>>(f, fw, fbias, out, s);
}